// round 12
// baseline (speedup 1.0000x reference)
#include <cuda_runtime.h>
#include <cuda_fp16.h>
#include <math.h>
#include <stdint.h>

#define T_STEPS 16384
#define NNODES  97
#define HID     6
#define ROWS_PAD (T_STEPS * 8)     // 131072 padded rows (8 h-slots per t)

#define NCHUNK  256
#define CHUNK   64
#define WARM    96

#define K1   112                    // conv1 K: 97 ci -> pad 112 (7 k16 chunks)
#define K23  208                    // conv2/3 K: 194 -> pad 208 (13 chunks)

// conv smem layout (words): 3 stages of [A(hi)1560 | A(lo)1560 | B 2496]
#define SA_WORDS      1560          // 130 rows * 12 words
#define STAGE_WORDS   5616          // 2*1560 + 2496
#define OFF_BIAS      16848         // 3 * 5616 (beyond the staging region)
#define CONV_SMEM_B   ((OFF_BIAS + 104) * 4)   // 67808 bytes

// ---------------- scratch (device globals; zero-initialized .bss) ----------
// Pad rows (slots 0,7) and pad K columns are NEVER written -> stay zero.
__device__ unsigned short g_R1h[(size_t)ROWS_PAD * K1];
__device__ unsigned short g_R1l[(size_t)ROWS_PAD * K1];
__device__ unsigned short g_R2h[(size_t)ROWS_PAD * K23];
__device__ unsigned short g_R2l[(size_t)ROWS_PAD * K23];
__device__ unsigned short g_R3h[(size_t)ROWS_PAD * K23];
__device__ unsigned short g_R3l[(size_t)ROWS_PAD * K23];
__device__ float g_c3[(size_t)T_STEPS * 582];
__device__ float g_part[1024 * 194];           // per-CTA (sum[97], sumsq[97])
__device__ unsigned int g_B1[7  * 26 * 192];   // [kc][nf][tap][lane][reg], fp16x2
__device__ unsigned int g_B2[13 * 26 * 192];
__device__ unsigned int g_B3[13 * 13 * 192];
__device__ float g_scale[NNODES];
__device__ float g_shift[NNODES];

// ---------------- helpers ---------------------------------------------------
__device__ __forceinline__ float sigf(float x) {
    return __fdividef(1.f, 1.f + __expf(-x));
}
__device__ __forceinline__ float tanh_f(float x) {
    float e = __expf(-2.f * fabsf(x));
    return copysignf(__fdividef(1.f - e, 1.f + e), x);
}
__device__ __forceinline__ uint32_t smem_u32(const void* p) {
    uint32_t a;
    asm("{ .reg .u64 t; cvta.to.shared.u64 t, %1; cvt.u32.u64 %0, t; }" : "=r"(a) : "l"(p));
    return a;
}
__device__ __forceinline__ uint64_t gptr(const void* p) {
    uint64_t g;
    asm("cvta.to.global.u64 %0, %1;" : "=l"(g) : "l"(p));
    return g;
}
__device__ __forceinline__ unsigned short f16_bits(float v) {
    __half h = __float2half_rn(v);
    return *reinterpret_cast<unsigned short*>(&h);
}
__device__ __forceinline__ float f16_val(unsigned short u) {
    __half h = *reinterpret_cast<__half*>(&u);
    return __half2float(h);
}
__device__ __forceinline__ void ldmx4(uint32_t* r, uint32_t addr) {
    asm volatile("ldmatrix.sync.aligned.m8n8.x4.shared.b16 {%0,%1,%2,%3}, [%4];"
                 : "=r"(r[0]), "=r"(r[1]), "=r"(r[2]), "=r"(r[3]) : "r"(addr));
}
__device__ __forceinline__ void mma_f16(float* d, const uint32_t* a, uint32_t b0, uint32_t b1) {
    asm volatile(
        "mma.sync.aligned.m16n8k16.row.col.f32.f16.f16.f32 "
        "{%0,%1,%2,%3}, {%4,%5,%6,%7}, {%8,%9}, {%0,%1,%2,%3};"
        : "+f"(d[0]), "+f"(d[1]), "+f"(d[2]), "+f"(d[3])
        : "r"(a[0]), "r"(a[1]), "r"(a[2]), "r"(a[3]), "r"(b0), "r"(b1));
}
template <int N>
__device__ __forceinline__ void cp_wait() {
    asm volatile("cp.async.wait_group %0;" :: "n"(N) : "memory");
}

// ---------------- K0: pack tap weights into mma B-fragment layout (fp16) ----
__global__ void pack_B(const float* __restrict__ Wc1,
                       const float* __restrict__ Wc2,
                       const float* __restrict__ Wc3) {
    const int N1 = 7 * 26 * 192, N2 = 13 * 26 * 192, N3 = 13 * 13 * 192;
    int idx = blockIdx.x * 256 + threadIdx.x;
    const float* W; unsigned int* dst; int NFALL, CIN, COUT, li;
    if (idx < N1)           { W = Wc1; dst = g_B1; NFALL = 26; CIN = 97;  COUT = 194; li = idx; }
    else if (idx < N1 + N2) { W = Wc2; dst = g_B2; NFALL = 26; CIN = 194; COUT = 194; li = idx - N1; }
    else if (idx < N1 + N2 + N3) { W = Wc3; dst = g_B3; NFALL = 13; CIN = 194; COUT = 97; li = idx - N1 - N2; }
    else return;

    int reg   = li & 1;
    int lane  = (li >> 1) & 31;
    int tap   = (li >> 6) % 3;
    int nf    = (li / 192) % NFALL;
    int kc    = li / (192 * NFALL);

    int n  = nf * 8 + (lane >> 2);
    int k0 = kc * 16 + (lane & 3) * 2 + reg * 8;
    float w0 = 0.f, w1 = 0.f;
    if (n < COUT) {
        if (k0 < CIN)     w0 = W[((n * CIN + k0) * 3 + tap) * 3 + 1];
        if (k0 + 1 < CIN) w1 = W[((n * CIN + k0 + 1) * 3 + tap) * 3 + 1];
    }
    dst[li] = (unsigned int)f16_bits(w0) | ((unsigned int)f16_bits(w1) << 16);
}

// ---------------- K1: fused x-projection + chunked LSTM ---------------------
__global__ void lstm_kernel(const float* __restrict__ X,
                            const float* __restrict__ Wih,
                            const float* __restrict__ bih,
                            const float* __restrict__ bhh,
                            const float* __restrict__ Whh,
                            unsigned short* __restrict__ R1h,
                            unsigned short* __restrict__ R1l) {
    int lane = threadIdx.x & 31;
    int w    = threadIdx.x >> 5;
    int g    = lane / 6;
    int j    = lane % 6;
    int node = blockIdx.y * 25 + w * 5 + g;
    bool active = (lane < 30) && (node < NNODES);
    int nn = active ? node : 0;

    float Wx[4][12], Wr[4][6], bsum[4];
#pragma unroll
    for (int gi = 0; gi < 4; ++gi) {
        int row = gi * 6 + j;
        bsum[gi] = __ldg(&bih[row]) + __ldg(&bhh[row]);
#pragma unroll
        for (int f = 0; f < 12; ++f) Wx[gi][f] = __ldg(&Wih[row * 12 + f]);
#pragma unroll
        for (int k = 0; k < 6; ++k)  Wr[gi][k] = __ldg(&Whh[row * 6 + k]);
    }

    float h = 0.f, c = 0.f;
    int t0 = blockIdx.x * CHUNK;
    int tb = t0 - WARM; if (tb < 0) tb = 0;
    int te = t0 + CHUNK;
    int base = g * 6;

    float2 xs[2][8];
#pragma unroll
    for (int u = 0; u < 8; ++u)
        xs[0][u] = __ldg(reinterpret_cast<const float2*>(
            X + ((size_t)(tb + u) * NNODES + nn) * 12 + 2 * j));

    int pb = 0;
    for (int tB = tb; tB < te; tB += 8, pb ^= 1) {
        if (tB + 8 < te) {
#pragma unroll
            for (int u = 0; u < 8; ++u)
                xs[pb ^ 1][u] = __ldg(reinterpret_cast<const float2*>(
                    X + ((size_t)(tB + 8 + u) * NNODES + nn) * 12 + 2 * j));
        }
#pragma unroll
        for (int u = 0; u < 8; ++u) {
            int t = tB + u;
            float2 xp = xs[pb][u];
            float xv[12];
#pragma unroll
            for (int m = 0; m < 6; ++m) {
                xv[2 * m]     = __shfl_sync(0xffffffffu, xp.x, base + m);
                xv[2 * m + 1] = __shfl_sync(0xffffffffu, xp.y, base + m);
            }
            float gate[4];
#pragma unroll
            for (int gi = 0; gi < 4; ++gi) {
                float s = bsum[gi];
#pragma unroll
                for (int f = 0; f < 12; ++f) s = fmaf(Wx[gi][f], xv[f], s);
                gate[gi] = s;
            }
            float hs[6];
#pragma unroll
            for (int k = 0; k < 6; ++k) hs[k] = __shfl_sync(0xffffffffu, h, base + k);
#pragma unroll
            for (int k = 0; k < 6; ++k) {
                gate[0] = fmaf(Wr[0][k], hs[k], gate[0]);
                gate[1] = fmaf(Wr[1][k], hs[k], gate[1]);
                gate[2] = fmaf(Wr[2][k], hs[k], gate[2]);
                gate[3] = fmaf(Wr[3][k], hs[k], gate[3]);
            }
            float ai = sigf(gate[0]), af = sigf(gate[1]);
            float ag = tanh_f(gate[2]), ao = sigf(gate[3]);
            c = fmaf(af, c, ai * ag);
            h = tanh_f(ao * tanh_f(c));
            if (t >= t0 && active) {
                size_t p = ((size_t)t * 8 + j + 1) * K1 + node;
                unsigned short hb = f16_bits(h);
                R1h[p] = hb;
                R1l[p] = f16_bits(h - f16_val(hb));
            }
        }
    }
}

// ---------------- conv tile prefetch via cp.async (128 threads) -------------
template <int KPAD, int NFALL>
__device__ __forceinline__ void conv_prefetch(
    const unsigned short* Rh, const unsigned short* Rl,
    const unsigned int* Bpk, int m0, int ycol, int kc, int stage,
    int tid, uint32_t sbase) {
    const uint32_t soff = sbase + (uint32_t)(stage * STAGE_WORDS * 4);
#pragma unroll 1
    for (int i = tid; i < 520; i += 128) {
        int row = i >> 2, sub = i & 3;
        int split = sub >> 1, half = sub & 1;
        int r = m0 - 1 + row;
        int ok = (r >= 0 && r < ROWS_PAD);
        int rc = ok ? r : 0;
        const unsigned short* src = (split ? Rl : Rh) +
            (size_t)rc * KPAD + kc * 16 + half * 8;
        uint32_t dst = soff +
            (uint32_t)((split * SA_WORDS + row * 12 + half * 4) * 4);
        unsigned sz = ok ? 16u : 0u;
        asm volatile("cp.async.cg.shared.global [%0], [%1], 16, %2;"
                     :: "r"(dst), "l"(gptr(src)), "r"(sz) : "memory");
    }
    const unsigned int* bsrc = Bpk + ((size_t)kc * NFALL + ycol * 13) * 192;
#pragma unroll 1
    for (int i = tid; i < 624; i += 128) {
        uint32_t dst = soff + (uint32_t)((2 * SA_WORDS + i * 4) * 4);
        asm volatile("cp.async.cg.shared.global [%0], [%1], 16, %2;"
                     :: "r"(dst), "l"(gptr(bsrc + i * 4)), "r"(16u) : "memory");
    }
    asm volatile("cp.async.commit_group;" ::: "memory");
}

// ---------------- K3: tap-decomposed conv GEMM, fp16, m32/warp --------------
// CTA tile: M=128 x N=104; 4 warps x m32 (2 m-frags each); 3-stage cp.async
// ring. A and B fragments double-buffered across taps (regs plentiful at
// 2 CTAs x 128 threads). 26 independent MMAs per burst.
template <int KPAD, int COUT, int NFALL, int ONPAD, bool LAST>
__global__ void __launch_bounds__(128, 2)
conv_mma(const unsigned short* __restrict__ Rh, const unsigned short* __restrict__ Rl,
         const unsigned int* __restrict__ Bpk, const float* __restrict__ bias,
         unsigned short* __restrict__ Oh, unsigned short* __restrict__ Ol,
         float* __restrict__ Oc, float* __restrict__ Part) {
    extern __shared__ unsigned int smw[];
    const uint32_t sbase = smem_u32(smw);
    float* s_bias = reinterpret_cast<float*>(smw + OFF_BIAS);

    const int tid = threadIdx.x, warp = tid >> 5, lane = tid & 31;
    const int m0  = blockIdx.x * 128;
    const int co0 = blockIdx.y * 104;
    if (tid < 104) s_bias[tid] = (co0 + tid < COUT) ? __ldg(&bias[co0 + tid]) : 0.f;

    float acc[2][13][4];
#pragma unroll
    for (int mf = 0; mf < 2; ++mf)
#pragma unroll
        for (int nf = 0; nf < 13; ++nf)
#pragma unroll
            for (int j = 0; j < 4; ++j) acc[mf][nf][j] = 0.f;

    const int NK = KPAD / 16;
    conv_prefetch<KPAD, NFALL>(Rh, Rl, Bpk, m0, blockIdx.y, 0, 0, tid, sbase);
    conv_prefetch<KPAD, NFALL>(Rh, Rl, Bpk, m0, blockIdx.y, 1, 1, tid, sbase);

    const int rowk = lane & 15;
    const uint32_t acolw4 = (uint32_t)((lane >> 4) * 16);   // byte offset

    for (int kc = 0; kc < NK; ++kc) {
        if (kc + 1 < NK) cp_wait<1>(); else cp_wait<0>();
        __syncthreads();
        if (kc + 2 < NK)
            conv_prefetch<KPAD, NFALL>(Rh, Rl, Bpk, m0, blockIdx.y,
                                       kc + 2, (kc + 2) % 3, tid, sbase);
        const int st = kc % 3;
        const uint32_t aoff = sbase + (uint32_t)(st * STAGE_WORDS * 4);
        const unsigned int* sb = &smw[st * STAGE_WORDS + 2 * SA_WORDS];

        uint32_t ah[2][2][4];       // [buf][mfrag][4]
        uint2    bb[2][13];
        // tap 0 operands
#pragma unroll
        for (int mf = 0; mf < 2; ++mf) {
            uint32_t ad = aoff +
                (uint32_t)(((warp * 32 + mf * 16 + rowk) * 12) * 4) + acolw4;
            ldmx4(ah[0][mf], ad);
        }
#pragma unroll
        for (int nf = 0; nf < 13; ++nf)
            bb[0][nf] = *reinterpret_cast<const uint2*>(&sb[nf * 3 * 64 + lane * 2]);

#pragma unroll
        for (int tap = 0; tap < 3; ++tap) {
            const int cur = tap & 1, nxt = cur ^ 1;
            uint32_t al[2][4];
#pragma unroll
            for (int mf = 0; mf < 2; ++mf) {
                uint32_t ad = aoff +
                    (uint32_t)(((warp * 32 + mf * 16 + tap + rowk) * 12 + SA_WORDS) * 4)
                    + acolw4;
                ldmx4(al[mf], ad);
            }
            if (tap < 2) {   // prefetch next tap's A-hi + B during this tap's MMAs
#pragma unroll
                for (int mf = 0; mf < 2; ++mf) {
                    uint32_t ad = aoff +
                        (uint32_t)(((warp * 32 + mf * 16 + tap + 1 + rowk) * 12) * 4)
                        + acolw4;
                    ldmx4(ah[nxt][mf], ad);
                }
#pragma unroll
                for (int nf = 0; nf < 13; ++nf)
                    bb[nxt][nf] = *reinterpret_cast<const uint2*>(
                        &sb[(nf * 3 + tap + 1) * 64 + lane * 2]);
            }
#pragma unroll
            for (int nf = 0; nf < 13; ++nf) {
                mma_f16(acc[0][nf], ah[cur][0], bb[cur][nf].x, bb[cur][nf].y);
                mma_f16(acc[1][nf], ah[cur][1], bb[cur][nf].x, bb[cur][nf].y);
            }
#pragma unroll
            for (int nf = 0; nf < 13; ++nf) {
                mma_f16(acc[0][nf], al[0], bb[cur][nf].x, bb[cur][nf].y);
                mma_f16(acc[1][nf], al[1], bb[cur][nf].x, bb[cur][nf].y);
            }
        }
    }

    // ---- staged epilogue ----
    __syncthreads();                 // all ldmatrix reads done; reuse smem
    if (LAST) {
        float* sOutF = reinterpret_cast<float*>(smw);   // [128][104]
#pragma unroll
        for (int mf = 0; mf < 2; ++mf)
#pragma unroll
            for (int nf = 0; nf < 13; ++nf)
#pragma unroll
                for (int j = 0; j < 4; ++j) {
                    int row = warp * 32 + mf * 16 + (lane >> 2) + (j >> 1) * 8;
                    int n = nf * 8 + (lane & 3) * 2 + (j & 1);
                    sOutF[row * 104 + n] = fmaxf(acc[mf][nf][j] + s_bias[n], 0.f);
                }
        __syncthreads();
        for (int idx = tid; idx < 16 * 582; idx += 128) {
            int tl = idx / 582, r = idx - tl * 582;
            int co = r / 6, sl = r - co * 6;
            Oc[((size_t)(m0 >> 3) + tl) * 582 + r] =
                sOutF[(tl * 8 + sl + 1) * 104 + co];
        }
        // per-CTA BN partial sums (deterministic fixed order)
        if (tid < 97) {
            float s = 0.f, q = 0.f;
#pragma unroll 1
            for (int tl = 0; tl < 16; ++tl)
#pragma unroll
                for (int sl = 0; sl < 6; ++sl) {
                    float v = sOutF[(tl * 8 + sl + 1) * 104 + tid];
                    s += v;
                    q = fmaf(v, v, q);
                }
            Part[blockIdx.x * 194 + tid] = s;
            Part[blockIdx.x * 194 + 97 + tid] = q;
        }
    } else {
        unsigned short* sOut = reinterpret_cast<unsigned short*>(smw); // [2][128][104]
#pragma unroll
        for (int mf = 0; mf < 2; ++mf)
#pragma unroll
            for (int nf = 0; nf < 13; ++nf)
#pragma unroll
                for (int j = 0; j < 4; ++j) {
                    int row = warp * 32 + mf * 16 + (lane >> 2) + (j >> 1) * 8;
                    int n = nf * 8 + (lane & 3) * 2 + (j & 1);
                    float v = fmaxf(acc[mf][nf][j] + s_bias[n], 0.f);
                    unsigned short hb = f16_bits(v);
                    sOut[row * 104 + n] = hb;
                    sOut[13312 + row * 104 + n] = f16_bits(v - f16_val(hb));
                }
        __syncthreads();
        unsigned int* OhW = reinterpret_cast<unsigned int*>(Oh);
        unsigned int* OlW = reinterpret_cast<unsigned int*>(Ol);
        const unsigned int* sOutW = smw;
        for (int idx = tid; idx < 2 * 128 * 52; idx += 128) {
            int wd = idx % 52; int rest = idx / 52;
            int row = rest & 127; int arr = rest >> 7;
            int slot = row & 7;                    // m0 multiple of 128
            if (slot < 1 || slot > 6) continue;
            unsigned int val = sOutW[arr * 6656 + row * 52 + wd];
            unsigned int* dst = arr ? OlW : OhW;
            dst[(((size_t)(m0 + row) * ONPAD + co0) >> 1) + wd] = val;
        }
    }
}

// ---------------- K4: BN stats phase 2 (reduce 1024 partials/channel) ------
__global__ void bnstats2_kernel(const float* __restrict__ gamma,
                                const float* __restrict__ beta) {
    __shared__ double s_s[256], s_q[256];
    int n = blockIdx.x;
    double s = 0.0, q = 0.0;
    for (int i = threadIdx.x; i < 1024; i += 256) {
        s += (double)g_part[i * 194 + n];
        q += (double)g_part[i * 194 + 97 + n];
    }
    s_s[threadIdx.x] = s; s_q[threadIdx.x] = q;
    __syncthreads();
    for (int st = 128; st > 0; st >>= 1) {
        if (threadIdx.x < st) {
            s_s[threadIdx.x] += s_s[threadIdx.x + st];
            s_q[threadIdx.x] += s_q[threadIdx.x + st];
        }
        __syncthreads();
    }
    if (threadIdx.x == 0) {
        double N = (double)T_STEPS * 6.0;
        double mean = s_s[0] / N;
        double var = s_q[0] / N - mean * mean;
        float sc = gamma[n] * (float)(1.0 / sqrt(var + 1e-5));
        g_scale[n] = sc;
        g_shift[n] = beta[n] - (float)mean * sc;
    }
}

// ---------------- K5: fused BN apply + linear ------------------------------
__global__ void final_kernel(const float* __restrict__ Wl,
                             const float* __restrict__ bl,
                             float* __restrict__ out) {
    __shared__ float s_wl[36], s_bl[6];
    if (threadIdx.x < 36) s_wl[threadIdx.x] = Wl[threadIdx.x];
    if (threadIdx.x < 6)  s_bl[threadIdx.x] = bl[threadIdx.x];
    __syncthreads();

    int nt = blockIdx.x * blockDim.x + threadIdx.x;
    if (nt >= T_STEPS * NNODES) return;
    int n = nt % NNODES;
    float sc = __ldg(&g_scale[n]), sh = __ldg(&g_shift[n]);
    const float* p = &g_c3[(size_t)nt * 6];
    float v[6];
#pragma unroll
    for (int hh = 0; hh < 6; ++hh) v[hh] = fmaf(p[hh], sc, sh);
#pragma unroll
    for (int j = 0; j < 6; ++j) {
        float o = s_bl[j];
#pragma unroll
        for (int hh = 0; hh < 6; ++hh) o = fmaf(v[hh], s_wl[j * 6 + hh], o);
        out[nt * 6 + j] = o;
    }
}

// ---------------- launch ----------------------------------------------------
extern "C" void kernel_launch(void* const* d_in, const int* in_sizes, int n_in,
                              void* d_out, int out_size) {
    const float* X    = (const float*)d_in[1];
    const float* Wih  = (const float*)d_in[3];
    const float* Whh  = (const float*)d_in[4];
    const float* bih  = (const float*)d_in[5];
    const float* bhh  = (const float*)d_in[6];
    const float* Wc1  = (const float*)d_in[7];
    const float* bc1  = (const float*)d_in[8];
    const float* Wc2  = (const float*)d_in[9];
    const float* bc2  = (const float*)d_in[10];
    const float* Wc3  = (const float*)d_in[11];
    const float* bc3  = (const float*)d_in[12];
    const float* gamma = (const float*)d_in[13];
    const float* beta  = (const float*)d_in[14];
    const float* Wl   = (const float*)d_in[15];
    const float* bl   = (const float*)d_in[16];
    float* out = (float*)d_out;

    unsigned short *r1h, *r1l, *r2h, *r2l, *r3h, *r3l;
    unsigned int *b1, *b2, *b3;
    float *c3, *part;
    cudaGetSymbolAddress((void**)&r1h, g_R1h);
    cudaGetSymbolAddress((void**)&r1l, g_R1l);
    cudaGetSymbolAddress((void**)&r2h, g_R2h);
    cudaGetSymbolAddress((void**)&r2l, g_R2l);
    cudaGetSymbolAddress((void**)&r3h, g_R3h);
    cudaGetSymbolAddress((void**)&r3l, g_R3l);
    cudaGetSymbolAddress((void**)&b1, g_B1);
    cudaGetSymbolAddress((void**)&b2, g_B2);
    cudaGetSymbolAddress((void**)&b3, g_B3);
    cudaGetSymbolAddress((void**)&c3, g_c3);
    cudaGetSymbolAddress((void**)&part, g_part);

    cudaFuncSetAttribute(conv_mma<K1, 194, 26, K23, false>,
                         cudaFuncAttributeMaxDynamicSharedMemorySize, CONV_SMEM_B);
    cudaFuncSetAttribute(conv_mma<K23, 194, 26, K23, false>,
                         cudaFuncAttributeMaxDynamicSharedMemorySize, CONV_SMEM_B);
    cudaFuncSetAttribute(conv_mma<K23, 97, 13, K23, true>,
                         cudaFuncAttributeMaxDynamicSharedMemorySize, CONV_SMEM_B);

    const int NPACK = (7 * 26 + 13 * 26 + 13 * 13) * 192;
    pack_B<<<(NPACK + 255) / 256, 256>>>(Wc1, Wc2, Wc3);
    lstm_kernel<<<dim3(NCHUNK, 4), 160>>>(X, Wih, bih, bhh, Whh, r1h, r1l);
    conv_mma<K1, 194, 26, K23, false>
        <<<dim3(1024, 2), 128, CONV_SMEM_B>>>(r1h, r1l, b1, bc1, r2h, r2l, nullptr, nullptr);
    conv_mma<K23, 194, 26, K23, false>
        <<<dim3(1024, 2), 128, CONV_SMEM_B>>>(r2h, r2l, b2, bc2, r3h, r3l, nullptr, nullptr);
    conv_mma<K23, 97, 13, K23, true>
        <<<dim3(1024, 1), 128, CONV_SMEM_B>>>(r3h, r3l, b3, bc3, nullptr, nullptr, c3, part);
    bnstats2_kernel<<<97, 256>>>(gamma, beta);
    final_kernel<<<(T_STEPS * NNODES + 255) / 256, 256>>>(Wl, bl, out);
}

// round 13
// speedup vs baseline: 1.0777x; 1.0777x over previous
#include <cuda_runtime.h>
#include <cuda_fp16.h>
#include <math.h>
#include <stdint.h>

#define T_STEPS 16384
#define NNODES  97
#define HID     6
#define ROWS_PAD (T_STEPS * 8)     // 131072 padded rows (8 h-slots per t)

#define NCHUNK  256
#define CHUNK   64
#define WARM    80

#define K1   112                    // conv1 K: 97 ci -> pad 112 (7 k16 chunks)
#define K23  208                    // conv2/3 K: 194 -> pad 208 (13 chunks)

// conv smem layout (words): 3 stages of [A(hi)1560 | A(lo)1560 | B 2496]
#define SA_WORDS      1560          // 130 rows * 12 words
#define STAGE_WORDS   5616          // 2*1560 + 2496
#define OFF_BIAS      16848         // 3 * 5616 (beyond the staging region)
#define CONV_SMEM_B   ((OFF_BIAS + 104) * 4)   // 67808 bytes

// ---------------- scratch (device globals; zero-initialized .bss) ----------
// Pad rows (slots 0,7) and pad K columns are NEVER written -> stay zero.
__device__ unsigned short g_R1h[(size_t)ROWS_PAD * K1];
__device__ unsigned short g_R1l[(size_t)ROWS_PAD * K1];
__device__ unsigned short g_R2h[(size_t)ROWS_PAD * K23];
__device__ unsigned short g_R2l[(size_t)ROWS_PAD * K23];
__device__ unsigned short g_R3h[(size_t)ROWS_PAD * K23];
__device__ unsigned short g_R3l[(size_t)ROWS_PAD * K23];
__device__ float g_c3[(size_t)T_STEPS * 582];
__device__ float g_part[1024 * 194];           // per-CTA (sum[97], sumsq[97])
__device__ unsigned int g_B1[7  * 26 * 192];   // [kc][nf][tap][lane][reg], fp16x2
__device__ unsigned int g_B2[13 * 26 * 192];
__device__ unsigned int g_B3[13 * 13 * 192];
__device__ float g_scale[NNODES];
__device__ float g_shift[NNODES];

// ---------------- helpers ---------------------------------------------------
__device__ __forceinline__ float sigf(float x) {
    return __fdividef(1.f, 1.f + __expf(-x));
}
__device__ __forceinline__ float tanh_f(float x) {
    float e = __expf(-2.f * fabsf(x));
    return copysignf(__fdividef(1.f - e, 1.f + e), x);
}
__device__ __forceinline__ uint32_t smem_u32(const void* p) {
    uint32_t a;
    asm("{ .reg .u64 t; cvta.to.shared.u64 t, %1; cvt.u32.u64 %0, t; }" : "=r"(a) : "l"(p));
    return a;
}
__device__ __forceinline__ uint64_t gptr(const void* p) {
    uint64_t g;
    asm("cvta.to.global.u64 %0, %1;" : "=l"(g) : "l"(p));
    return g;
}
__device__ __forceinline__ unsigned short f16_bits(float v) {
    __half h = __float2half_rn(v);
    return *reinterpret_cast<unsigned short*>(&h);
}
__device__ __forceinline__ float f16_val(unsigned short u) {
    __half h = *reinterpret_cast<__half*>(&u);
    return __half2float(h);
}
__device__ __forceinline__ void ldmx4(uint32_t* r, uint32_t addr) {
    asm volatile("ldmatrix.sync.aligned.m8n8.x4.shared.b16 {%0,%1,%2,%3}, [%4];"
                 : "=r"(r[0]), "=r"(r[1]), "=r"(r[2]), "=r"(r[3]) : "r"(addr));
}
__device__ __forceinline__ void mma_f16(float* d, const uint32_t* a, uint32_t b0, uint32_t b1) {
    asm volatile(
        "mma.sync.aligned.m16n8k16.row.col.f32.f16.f16.f32 "
        "{%0,%1,%2,%3}, {%4,%5,%6,%7}, {%8,%9}, {%0,%1,%2,%3};"
        : "+f"(d[0]), "+f"(d[1]), "+f"(d[2]), "+f"(d[3])
        : "r"(a[0]), "r"(a[1]), "r"(a[2]), "r"(a[3]), "r"(b0), "r"(b1));
}
template <int N>
__device__ __forceinline__ void cp_wait() {
    asm volatile("cp.async.wait_group %0;" :: "n"(N) : "memory");
}

// ---------------- K0: pack tap weights into mma B-fragment layout (fp16) ----
__global__ void pack_B(const float* __restrict__ Wc1,
                       const float* __restrict__ Wc2,
                       const float* __restrict__ Wc3) {
    const int N1 = 7 * 26 * 192, N2 = 13 * 26 * 192, N3 = 13 * 13 * 192;
    int idx = blockIdx.x * 256 + threadIdx.x;
    const float* W; unsigned int* dst; int NFALL, CIN, COUT, li;
    if (idx < N1)           { W = Wc1; dst = g_B1; NFALL = 26; CIN = 97;  COUT = 194; li = idx; }
    else if (idx < N1 + N2) { W = Wc2; dst = g_B2; NFALL = 26; CIN = 194; COUT = 194; li = idx - N1; }
    else if (idx < N1 + N2 + N3) { W = Wc3; dst = g_B3; NFALL = 13; CIN = 194; COUT = 97; li = idx - N1 - N2; }
    else return;

    int reg   = li & 1;
    int lane  = (li >> 1) & 31;
    int tap   = (li >> 6) % 3;
    int nf    = (li / 192) % NFALL;
    int kc    = li / (192 * NFALL);

    int n  = nf * 8 + (lane >> 2);
    int k0 = kc * 16 + (lane & 3) * 2 + reg * 8;
    float w0 = 0.f, w1 = 0.f;
    if (n < COUT) {
        if (k0 < CIN)     w0 = W[((n * CIN + k0) * 3 + tap) * 3 + 1];
        if (k0 + 1 < CIN) w1 = W[((n * CIN + k0 + 1) * 3 + tap) * 3 + 1];
    }
    dst[li] = (unsigned int)f16_bits(w0) | ((unsigned int)f16_bits(w1) << 16);
}

// ---------------- K1: fused x-projection + chunked LSTM ---------------------
__global__ void lstm_kernel(const float* __restrict__ X,
                            const float* __restrict__ Wih,
                            const float* __restrict__ bih,
                            const float* __restrict__ bhh,
                            const float* __restrict__ Whh,
                            unsigned short* __restrict__ R1h,
                            unsigned short* __restrict__ R1l) {
    int lane = threadIdx.x & 31;
    int w    = threadIdx.x >> 5;
    int g    = lane / 6;
    int j    = lane % 6;
    int node = blockIdx.y * 25 + w * 5 + g;
    bool active = (lane < 30) && (node < NNODES);
    int nn = active ? node : 0;

    float Wx[4][12], Wr[4][6], bsum[4];
#pragma unroll
    for (int gi = 0; gi < 4; ++gi) {
        int row = gi * 6 + j;
        bsum[gi] = __ldg(&bih[row]) + __ldg(&bhh[row]);
#pragma unroll
        for (int f = 0; f < 12; ++f) Wx[gi][f] = __ldg(&Wih[row * 12 + f]);
#pragma unroll
        for (int k = 0; k < 6; ++k)  Wr[gi][k] = __ldg(&Whh[row * 6 + k]);
    }

    float h = 0.f, c = 0.f;
    int t0 = blockIdx.x * CHUNK;
    int tb = t0 - WARM; if (tb < 0) tb = 0;
    int te = t0 + CHUNK;
    int base = g * 6;

    float2 xs[2][8];
#pragma unroll
    for (int u = 0; u < 8; ++u)
        xs[0][u] = __ldg(reinterpret_cast<const float2*>(
            X + ((size_t)(tb + u) * NNODES + nn) * 12 + 2 * j));

    int pb = 0;
    for (int tB = tb; tB < te; tB += 8, pb ^= 1) {
        if (tB + 8 < te) {
#pragma unroll
            for (int u = 0; u < 8; ++u)
                xs[pb ^ 1][u] = __ldg(reinterpret_cast<const float2*>(
                    X + ((size_t)(tB + 8 + u) * NNODES + nn) * 12 + 2 * j));
        }
#pragma unroll
        for (int u = 0; u < 8; ++u) {
            int t = tB + u;
            float2 xp = xs[pb][u];
            float xv[12];
#pragma unroll
            for (int m = 0; m < 6; ++m) {
                xv[2 * m]     = __shfl_sync(0xffffffffu, xp.x, base + m);
                xv[2 * m + 1] = __shfl_sync(0xffffffffu, xp.y, base + m);
            }
            float gate[4];
#pragma unroll
            for (int gi = 0; gi < 4; ++gi) {
                float s = bsum[gi];
#pragma unroll
                for (int f = 0; f < 12; ++f) s = fmaf(Wx[gi][f], xv[f], s);
                gate[gi] = s;
            }
            float hs[6];
#pragma unroll
            for (int k = 0; k < 6; ++k) hs[k] = __shfl_sync(0xffffffffu, h, base + k);
#pragma unroll
            for (int k = 0; k < 6; ++k) {
                gate[0] = fmaf(Wr[0][k], hs[k], gate[0]);
                gate[1] = fmaf(Wr[1][k], hs[k], gate[1]);
                gate[2] = fmaf(Wr[2][k], hs[k], gate[2]);
                gate[3] = fmaf(Wr[3][k], hs[k], gate[3]);
            }
            float ai = sigf(gate[0]), af = sigf(gate[1]);
            float ag = tanh_f(gate[2]), ao = sigf(gate[3]);
            c = fmaf(af, c, ai * ag);
            h = tanh_f(ao * tanh_f(c));
            if (t >= t0 && active) {
                size_t p = ((size_t)t * 8 + j + 1) * K1 + node;
                unsigned short hb = f16_bits(h);
                R1h[p] = hb;
                R1l[p] = f16_bits(h - f16_val(hb));
            }
        }
    }
}

// ---------------- conv tile prefetch via cp.async (256 threads) -------------
template <int KPAD, int NFALL>
__device__ __forceinline__ void conv_prefetch(
    const unsigned short* Rh, const unsigned short* Rl,
    const unsigned int* Bpk, int m0, int ycol, int kc, int stage,
    int tid, uint32_t sbase) {
    const uint32_t soff = sbase + (uint32_t)(stage * STAGE_WORDS * 4);
#pragma unroll 1
    for (int i = tid; i < 520; i += 256) {
        int row = i >> 2, sub = i & 3;
        int split = sub >> 1, half = sub & 1;
        int r = m0 - 1 + row;
        int ok = (r >= 0 && r < ROWS_PAD);
        int rc = ok ? r : 0;
        const unsigned short* src = (split ? Rl : Rh) +
            (size_t)rc * KPAD + kc * 16 + half * 8;
        uint32_t dst = soff +
            (uint32_t)((split * SA_WORDS + row * 12 + half * 4) * 4);
        unsigned sz = ok ? 16u : 0u;
        asm volatile("cp.async.cg.shared.global [%0], [%1], 16, %2;"
                     :: "r"(dst), "l"(gptr(src)), "r"(sz) : "memory");
    }
    const unsigned int* bsrc = Bpk + ((size_t)kc * NFALL + ycol * 13) * 192;
#pragma unroll 1
    for (int i = tid; i < 624; i += 256) {
        uint32_t dst = soff + (uint32_t)((2 * SA_WORDS + i * 4) * 4);
        asm volatile("cp.async.cg.shared.global [%0], [%1], 16, %2;"
                     :: "r"(dst), "l"(gptr(bsrc + i * 4)), "r"(16u) : "memory");
    }
    asm volatile("cp.async.commit_group;" ::: "memory");
}

// ---------------- K3: tap-decomposed conv GEMM, fp16, reordered chunk -------
// CTA tile: M=128 x N=104; 8 warps x m16; 3-stage cp.async ring.
// Chunk body: sync -> tap0 operand loads -> prefetch(kc+2) -> MMA taps.
// kc loop unrolled by 3 so all stage addresses are compile-time constants.
template <int KPAD, int COUT, int NFALL, int ONPAD, bool LAST>
__global__ void __launch_bounds__(256, 2)
conv_mma(const unsigned short* __restrict__ Rh, const unsigned short* __restrict__ Rl,
         const unsigned int* __restrict__ Bpk, const float* __restrict__ bias,
         unsigned short* __restrict__ Oh, unsigned short* __restrict__ Ol,
         float* __restrict__ Oc, float* __restrict__ Part) {
    extern __shared__ unsigned int smw[];
    const uint32_t sbase = smem_u32(smw);
    float* s_bias = reinterpret_cast<float*>(smw + OFF_BIAS);

    const int tid = threadIdx.x, warp = tid >> 5, lane = tid & 31;
    const int m0  = blockIdx.x * 128;
    const int co0 = blockIdx.y * 104;
    if (tid < 104) s_bias[tid] = (co0 + tid < COUT) ? __ldg(&bias[co0 + tid]) : 0.f;

    float acc[13][4];
#pragma unroll
    for (int nf = 0; nf < 13; ++nf)
#pragma unroll
        for (int j = 0; j < 4; ++j) acc[nf][j] = 0.f;

    const int NK = KPAD / 16;
    conv_prefetch<KPAD, NFALL>(Rh, Rl, Bpk, m0, blockIdx.y, 0, 0, tid, sbase);
    conv_prefetch<KPAD, NFALL>(Rh, Rl, Bpk, m0, blockIdx.y, 1, 1, tid, sbase);

    const int rowk = lane & 15;
    const uint32_t acolw4 = (uint32_t)((lane >> 4) * 16);   // byte offset

    for (int kb = 0; kb < NK; kb += 3) {
#pragma unroll
        for (int s = 0; s < 3; ++s) {
            const int kc = kb + s;
            if (kc >= NK) continue;
            if (kc + 1 < NK) cp_wait<1>(); else cp_wait<0>();
            __syncthreads();

            const uint32_t aoff = sbase + (uint32_t)(s * STAGE_WORDS * 4);
            const unsigned int* sb = &smw[s * STAGE_WORDS + 2 * SA_WORDS];

            // tap0 operand loads FIRST (hide their latency under prefetch issue)
            uint32_t ah[2][4], al[2][4];
            {
                uint32_t ad = aoff +
                    (uint32_t)(((warp * 16 + rowk) * 12) * 4) + acolw4;
                ldmx4(ah[0], ad);
                ldmx4(al[0], ad + SA_WORDS * 4);
            }
            uint2 bb[13];
#pragma unroll
            for (int nf = 0; nf < 13; ++nf)
                bb[nf] = *reinterpret_cast<const uint2*>(
                    &sb[nf * 3 * 64 + lane * 2]);

            if (kc + 2 < NK)
                conv_prefetch<KPAD, NFALL>(Rh, Rl, Bpk, m0, blockIdx.y,
                                           kc + 2, (s + 2) % 3, tid, sbase);

#pragma unroll
            for (int tap = 0; tap < 3; ++tap) {
                const int cur = tap & 1, nxt = cur ^ 1;
                if (tap > 0) {
#pragma unroll
                    for (int nf = 0; nf < 13; ++nf)
                        bb[nf] = *reinterpret_cast<const uint2*>(
                            &sb[(nf * 3 + tap) * 64 + lane * 2]);
                }
                if (tap < 2) {   // prefetch next tap's A during this tap's MMAs
                    uint32_t ad = aoff +
                        (uint32_t)(((warp * 16 + tap + 1 + rowk) * 12) * 4) + acolw4;
                    ldmx4(ah[nxt], ad);
                    ldmx4(al[nxt], ad + SA_WORDS * 4);
                }
#pragma unroll
                for (int nf = 0; nf < 13; ++nf)
                    mma_f16(acc[nf], ah[cur], bb[nf].x, bb[nf].y);
#pragma unroll
                for (int nf = 0; nf < 13; ++nf)
                    mma_f16(acc[nf], al[cur], bb[nf].x, bb[nf].y);
            }
        }
    }

    // ---- staged epilogue ----
    __syncthreads();                 // all ldmatrix reads done; reuse smem
    if (LAST) {
        float* sOutF = reinterpret_cast<float*>(smw);   // [128][104]
#pragma unroll
        for (int nf = 0; nf < 13; ++nf)
#pragma unroll
            for (int j = 0; j < 4; ++j) {
                int row = warp * 16 + (lane >> 2) + (j >> 1) * 8;
                int n = nf * 8 + (lane & 3) * 2 + (j & 1);
                sOutF[row * 104 + n] = fmaxf(acc[nf][j] + s_bias[n], 0.f);
            }
        __syncthreads();
        for (int idx = tid; idx < 16 * 582; idx += 256) {
            int tl = idx / 582, r = idx - tl * 582;
            int co = r / 6, sl = r - co * 6;
            Oc[((size_t)(m0 >> 3) + tl) * 582 + r] =
                sOutF[(tl * 8 + sl + 1) * 104 + co];
        }
        // per-CTA BN partial sums (deterministic fixed order)
        if (tid < 97) {
            float s = 0.f, q = 0.f;
#pragma unroll 1
            for (int tl = 0; tl < 16; ++tl)
#pragma unroll
                for (int sl = 0; sl < 6; ++sl) {
                    float v = sOutF[(tl * 8 + sl + 1) * 104 + tid];
                    s += v;
                    q = fmaf(v, v, q);
                }
            Part[blockIdx.x * 194 + tid] = s;
            Part[blockIdx.x * 194 + 97 + tid] = q;
        }
    } else {
        unsigned short* sOut = reinterpret_cast<unsigned short*>(smw); // [2][128][104]
#pragma unroll
        for (int nf = 0; nf < 13; ++nf)
#pragma unroll
            for (int j = 0; j < 4; ++j) {
                int row = warp * 16 + (lane >> 2) + (j >> 1) * 8;
                int n = nf * 8 + (lane & 3) * 2 + (j & 1);
                float v = fmaxf(acc[nf][j] + s_bias[n], 0.f);
                unsigned short hb = f16_bits(v);
                sOut[row * 104 + n] = hb;
                sOut[13312 + row * 104 + n] = f16_bits(v - f16_val(hb));
            }
        __syncthreads();
        unsigned int* OhW = reinterpret_cast<unsigned int*>(Oh);
        unsigned int* OlW = reinterpret_cast<unsigned int*>(Ol);
        const unsigned int* sOutW = smw;
        for (int idx = tid; idx < 2 * 128 * 52; idx += 256) {
            int wd = idx % 52; int rest = idx / 52;
            int row = rest & 127; int arr = rest >> 7;
            int slot = row & 7;                    // m0 multiple of 128
            if (slot < 1 || slot > 6) continue;
            unsigned int val = sOutW[arr * 6656 + row * 52 + wd];
            unsigned int* dst = arr ? OlW : OhW;
            dst[(((size_t)(m0 + row) * ONPAD + co0) >> 1) + wd] = val;
        }
    }
}

// ---------------- K4: BN stats phase 2 (reduce 1024 partials/channel) ------
__global__ void bnstats2_kernel(const float* __restrict__ gamma,
                                const float* __restrict__ beta) {
    __shared__ double s_s[256], s_q[256];
    int n = blockIdx.x;
    double s = 0.0, q = 0.0;
    for (int i = threadIdx.x; i < 1024; i += 256) {
        s += (double)g_part[i * 194 + n];
        q += (double)g_part[i * 194 + 97 + n];
    }
    s_s[threadIdx.x] = s; s_q[threadIdx.x] = q;
    __syncthreads();
    for (int st = 128; st > 0; st >>= 1) {
        if (threadIdx.x < st) {
            s_s[threadIdx.x] += s_s[threadIdx.x + st];
            s_q[threadIdx.x] += s_q[threadIdx.x + st];
        }
        __syncthreads();
    }
    if (threadIdx.x == 0) {
        double N = (double)T_STEPS * 6.0;
        double mean = s_s[0] / N;
        double var = s_q[0] / N - mean * mean;
        float sc = gamma[n] * (float)(1.0 / sqrt(var + 1e-5));
        g_scale[n] = sc;
        g_shift[n] = beta[n] - (float)mean * sc;
    }
}

// ---------------- K5: fused BN apply + linear ------------------------------
__global__ void final_kernel(const float* __restrict__ Wl,
                             const float* __restrict__ bl,
                             float* __restrict__ out) {
    __shared__ float s_wl[36], s_bl[6];
    if (threadIdx.x < 36) s_wl[threadIdx.x] = Wl[threadIdx.x];
    if (threadIdx.x < 6)  s_bl[threadIdx.x] = bl[threadIdx.x];
    __syncthreads();

    int nt = blockIdx.x * blockDim.x + threadIdx.x;
    if (nt >= T_STEPS * NNODES) return;
    int n = nt % NNODES;
    float sc = __ldg(&g_scale[n]), sh = __ldg(&g_shift[n]);
    const float* p = &g_c3[(size_t)nt * 6];
    float v[6];
#pragma unroll
    for (int hh = 0; hh < 6; ++hh) v[hh] = fmaf(p[hh], sc, sh);
#pragma unroll
    for (int j = 0; j < 6; ++j) {
        float o = s_bl[j];
#pragma unroll
        for (int hh = 0; hh < 6; ++hh) o = fmaf(v[hh], s_wl[j * 6 + hh], o);
        out[nt * 6 + j] = o;
    }
}

// ---------------- launch ----------------------------------------------------
extern "C" void kernel_launch(void* const* d_in, const int* in_sizes, int n_in,
                              void* d_out, int out_size) {
    const float* X    = (const float*)d_in[1];
    const float* Wih  = (const float*)d_in[3];
    const float* Whh  = (const float*)d_in[4];
    const float* bih  = (const float*)d_in[5];
    const float* bhh  = (const float*)d_in[6];
    const float* Wc1  = (const float*)d_in[7];
    const float* bc1  = (const float*)d_in[8];
    const float* Wc2  = (const float*)d_in[9];
    const float* bc2  = (const float*)d_in[10];
    const float* Wc3  = (const float*)d_in[11];
    const float* bc3  = (const float*)d_in[12];
    const float* gamma = (const float*)d_in[13];
    const float* beta  = (const float*)d_in[14];
    const float* Wl   = (const float*)d_in[15];
    const float* bl   = (const float*)d_in[16];
    float* out = (float*)d_out;

    unsigned short *r1h, *r1l, *r2h, *r2l, *r3h, *r3l;
    unsigned int *b1, *b2, *b3;
    float *c3, *part;
    cudaGetSymbolAddress((void**)&r1h, g_R1h);
    cudaGetSymbolAddress((void**)&r1l, g_R1l);
    cudaGetSymbolAddress((void**)&r2h, g_R2h);
    cudaGetSymbolAddress((void**)&r2l, g_R2l);
    cudaGetSymbolAddress((void**)&r3h, g_R3h);
    cudaGetSymbolAddress((void**)&r3l, g_R3l);
    cudaGetSymbolAddress((void**)&b1, g_B1);
    cudaGetSymbolAddress((void**)&b2, g_B2);
    cudaGetSymbolAddress((void**)&b3, g_B3);
    cudaGetSymbolAddress((void**)&c3, g_c3);
    cudaGetSymbolAddress((void**)&part, g_part);

    cudaFuncSetAttribute(conv_mma<K1, 194, 26, K23, false>,
                         cudaFuncAttributeMaxDynamicSharedMemorySize, CONV_SMEM_B);
    cudaFuncSetAttribute(conv_mma<K23, 194, 26, K23, false>,
                         cudaFuncAttributeMaxDynamicSharedMemorySize, CONV_SMEM_B);
    cudaFuncSetAttribute(conv_mma<K23, 97, 13, K23, true>,
                         cudaFuncAttributeMaxDynamicSharedMemorySize, CONV_SMEM_B);

    const int NPACK = (7 * 26 + 13 * 26 + 13 * 13) * 192;
    pack_B<<<(NPACK + 255) / 256, 256>>>(Wc1, Wc2, Wc3);
    lstm_kernel<<<dim3(NCHUNK, 4), 160>>>(X, Wih, bih, bhh, Whh, r1h, r1l);
    conv_mma<K1, 194, 26, K23, false>
        <<<dim3(1024, 2), 256, CONV_SMEM_B>>>(r1h, r1l, b1, bc1, r2h, r2l, nullptr, nullptr);
    conv_mma<K23, 194, 26, K23, false>
        <<<dim3(1024, 2), 256, CONV_SMEM_B>>>(r2h, r2l, b2, bc2, r3h, r3l, nullptr, nullptr);
    conv_mma<K23, 97, 13, K23, true>
        <<<dim3(1024, 1), 256, CONV_SMEM_B>>>(r3h, r3l, b3, bc3, nullptr, nullptr, c3, part);
    bnstats2_kernel<<<97, 256>>>(gamma, beta);
    final_kernel<<<(T_STEPS * NNODES + 255) / 256, 256>>>(Wl, bl, out);
}

// round 14
// speedup vs baseline: 1.1685x; 1.0842x over previous
#include <cuda_runtime.h>
#include <cuda_fp16.h>
#include <math.h>
#include <stdint.h>

#define T_STEPS 16384
#define NNODES  97
#define HID     6
#define ROWS_PAD (T_STEPS * 8)     // 131072 padded rows (8 h-slots per t)

#define NCHUNK  256
#define CHUNK   64
#define WARM    64

#define K1   112                    // conv1 K: 97 ci -> pad 112 (7 k16 chunks)
#define K23  208                    // conv2/3 K: 194 -> pad 208 (13 chunks)

// conv smem layout (words): 2 stages of [A(hi)2600 | A(lo)2600 | B 4992]
// A row = 32 fp16 (16 words) + 4 pad words -> 20-word (80B) stride, odd*16B.
#define SA32_WORDS    2600          // 130 rows * 20 words
#define STAGE32_WORDS 10192         // 2*2600 + 4992
#define OFF_BIAS32    20384         // 2 * 10192
#define CONV_SMEM32   ((OFF_BIAS32 + 104) * 4)   // 81952 bytes

// ---------------- scratch (device globals; zero-initialized .bss) ----------
// Pad rows (slots 0,7) and pad K columns are NEVER written -> stay zero.
__device__ unsigned short g_R1h[(size_t)ROWS_PAD * K1];
__device__ unsigned short g_R1l[(size_t)ROWS_PAD * K1];
__device__ unsigned short g_R2h[(size_t)ROWS_PAD * K23];
__device__ unsigned short g_R2l[(size_t)ROWS_PAD * K23];
__device__ unsigned short g_R3h[(size_t)ROWS_PAD * K23];
__device__ unsigned short g_R3l[(size_t)ROWS_PAD * K23];
__device__ float g_c3[(size_t)T_STEPS * 582];
__device__ float g_part[1024 * 194];           // per-CTA (sum[97], sumsq[97])
__device__ unsigned int g_B1[7  * 26 * 192];   // [kc16][nf][tap][lane][reg], fp16x2
__device__ unsigned int g_B2[13 * 26 * 192];
__device__ unsigned int g_B3[13 * 13 * 192];
__device__ float g_scale[NNODES];
__device__ float g_shift[NNODES];

// ---------------- helpers ---------------------------------------------------
__device__ __forceinline__ float sigf(float x) {
    return __fdividef(1.f, 1.f + __expf(-x));
}
__device__ __forceinline__ float tanh_f(float x) {
    float e = __expf(-2.f * fabsf(x));
    return copysignf(__fdividef(1.f - e, 1.f + e), x);
}
__device__ __forceinline__ uint32_t smem_u32(const void* p) {
    uint32_t a;
    asm("{ .reg .u64 t; cvta.to.shared.u64 t, %1; cvt.u32.u64 %0, t; }" : "=r"(a) : "l"(p));
    return a;
}
__device__ __forceinline__ uint64_t gptr(const void* p) {
    uint64_t g;
    asm("cvta.to.global.u64 %0, %1;" : "=l"(g) : "l"(p));
    return g;
}
__device__ __forceinline__ unsigned short f16_bits(float v) {
    __half h = __float2half_rn(v);
    return *reinterpret_cast<unsigned short*>(&h);
}
__device__ __forceinline__ float f16_val(unsigned short u) {
    __half h = *reinterpret_cast<__half*>(&u);
    return __half2float(h);
}
__device__ __forceinline__ void ldmx4(uint32_t* r, uint32_t addr) {
    asm volatile("ldmatrix.sync.aligned.m8n8.x4.shared.b16 {%0,%1,%2,%3}, [%4];"
                 : "=r"(r[0]), "=r"(r[1]), "=r"(r[2]), "=r"(r[3]) : "r"(addr));
}
__device__ __forceinline__ void mma_f16(float* d, const uint32_t* a, uint32_t b0, uint32_t b1) {
    asm volatile(
        "mma.sync.aligned.m16n8k16.row.col.f32.f16.f16.f32 "
        "{%0,%1,%2,%3}, {%4,%5,%6,%7}, {%8,%9}, {%0,%1,%2,%3};"
        : "+f"(d[0]), "+f"(d[1]), "+f"(d[2]), "+f"(d[3])
        : "r"(a[0]), "r"(a[1]), "r"(a[2]), "r"(a[3]), "r"(b0), "r"(b1));
}
template <int N>
__device__ __forceinline__ void cp_wait() {
    asm volatile("cp.async.wait_group %0;" :: "n"(N) : "memory");
}

// ---------------- K0: pack tap weights into mma B-fragment layout (fp16) ----
__global__ void pack_B(const float* __restrict__ Wc1,
                       const float* __restrict__ Wc2,
                       const float* __restrict__ Wc3) {
    const int N1 = 7 * 26 * 192, N2 = 13 * 26 * 192, N3 = 13 * 13 * 192;
    int idx = blockIdx.x * 256 + threadIdx.x;
    const float* W; unsigned int* dst; int NFALL, CIN, COUT, li;
    if (idx < N1)           { W = Wc1; dst = g_B1; NFALL = 26; CIN = 97;  COUT = 194; li = idx; }
    else if (idx < N1 + N2) { W = Wc2; dst = g_B2; NFALL = 26; CIN = 194; COUT = 194; li = idx - N1; }
    else if (idx < N1 + N2 + N3) { W = Wc3; dst = g_B3; NFALL = 13; CIN = 194; COUT = 97; li = idx - N1 - N2; }
    else return;

    int reg   = li & 1;
    int lane  = (li >> 1) & 31;
    int tap   = (li >> 6) % 3;
    int nf    = (li / 192) % NFALL;
    int kc    = li / (192 * NFALL);

    int n  = nf * 8 + (lane >> 2);
    int k0 = kc * 16 + (lane & 3) * 2 + reg * 8;
    float w0 = 0.f, w1 = 0.f;
    if (n < COUT) {
        if (k0 < CIN)     w0 = W[((n * CIN + k0) * 3 + tap) * 3 + 1];
        if (k0 + 1 < CIN) w1 = W[((n * CIN + k0 + 1) * 3 + tap) * 3 + 1];
    }
    dst[li] = (unsigned int)f16_bits(w0) | ((unsigned int)f16_bits(w1) << 16);
}

// ---------------- K1: fused x-projection + chunked LSTM ---------------------
__global__ void lstm_kernel(const float* __restrict__ X,
                            const float* __restrict__ Wih,
                            const float* __restrict__ bih,
                            const float* __restrict__ bhh,
                            const float* __restrict__ Whh,
                            unsigned short* __restrict__ R1h,
                            unsigned short* __restrict__ R1l) {
    int lane = threadIdx.x & 31;
    int w    = threadIdx.x >> 5;
    int g    = lane / 6;
    int j    = lane % 6;
    int node = blockIdx.y * 25 + w * 5 + g;
    bool active = (lane < 30) && (node < NNODES);
    int nn = active ? node : 0;

    float Wx[4][12], Wr[4][6], bsum[4];
#pragma unroll
    for (int gi = 0; gi < 4; ++gi) {
        int row = gi * 6 + j;
        bsum[gi] = __ldg(&bih[row]) + __ldg(&bhh[row]);
#pragma unroll
        for (int f = 0; f < 12; ++f) Wx[gi][f] = __ldg(&Wih[row * 12 + f]);
#pragma unroll
        for (int k = 0; k < 6; ++k)  Wr[gi][k] = __ldg(&Whh[row * 6 + k]);
    }

    float h = 0.f, c = 0.f;
    int t0 = blockIdx.x * CHUNK;
    int tb = t0 - WARM; if (tb < 0) tb = 0;
    int te = t0 + CHUNK;
    int base = g * 6;

    float2 xs[2][8];
#pragma unroll
    for (int u = 0; u < 8; ++u)
        xs[0][u] = __ldg(reinterpret_cast<const float2*>(
            X + ((size_t)(tb + u) * NNODES + nn) * 12 + 2 * j));

    int pb = 0;
    for (int tB = tb; tB < te; tB += 8, pb ^= 1) {
        if (tB + 8 < te) {
#pragma unroll
            for (int u = 0; u < 8; ++u)
                xs[pb ^ 1][u] = __ldg(reinterpret_cast<const float2*>(
                    X + ((size_t)(tB + 8 + u) * NNODES + nn) * 12 + 2 * j));
        }
#pragma unroll
        for (int u = 0; u < 8; ++u) {
            int t = tB + u;
            float2 xp = xs[pb][u];
            float xv[12];
#pragma unroll
            for (int m = 0; m < 6; ++m) {
                xv[2 * m]     = __shfl_sync(0xffffffffu, xp.x, base + m);
                xv[2 * m + 1] = __shfl_sync(0xffffffffu, xp.y, base + m);
            }
            float gate[4];
#pragma unroll
            for (int gi = 0; gi < 4; ++gi) {
                float s = bsum[gi];
#pragma unroll
                for (int f = 0; f < 12; ++f) s = fmaf(Wx[gi][f], xv[f], s);
                gate[gi] = s;
            }
            float hs[6];
#pragma unroll
            for (int k = 0; k < 6; ++k) hs[k] = __shfl_sync(0xffffffffu, h, base + k);
#pragma unroll
            for (int k = 0; k < 6; ++k) {
                gate[0] = fmaf(Wr[0][k], hs[k], gate[0]);
                gate[1] = fmaf(Wr[1][k], hs[k], gate[1]);
                gate[2] = fmaf(Wr[2][k], hs[k], gate[2]);
                gate[3] = fmaf(Wr[3][k], hs[k], gate[3]);
            }
            float ai = sigf(gate[0]), af = sigf(gate[1]);
            float ag = tanh_f(gate[2]), ao = sigf(gate[3]);
            c = fmaf(af, c, ai * ag);
            h = tanh_f(ao * tanh_f(c));
            if (t >= t0 && active) {
                size_t p = ((size_t)t * 8 + j + 1) * K1 + node;
                unsigned short hb = f16_bits(h);
                R1h[p] = hb;
                R1l[p] = f16_bits(h - f16_val(hb));
            }
        }
    }
}

// ---------------- conv k32 stage prefetch via cp.async ----------------------
// A tile: 130 rows x 32 fp16 per split (hi/lo); B: 2 k16 sub-slices (13 nf each).
template <int KPAD, int KR16, int NFALL>
__device__ __forceinline__ void conv_prefetch32(
    const unsigned short* Rh, const unsigned short* Rl,
    const unsigned int* Bpk, int m0, int ycol, int kc32, int stage,
    int tid, uint32_t sbase) {
    const uint32_t soff = sbase + (uint32_t)(stage * STAGE32_WORDS * 4);
    // A: 130 rows * 2 splits * 4 quarters (16B each)
#pragma unroll 1
    for (int i = tid; i < 1040; i += 256) {
        int row = i >> 3, r = i & 7;
        int split = r >> 2, q = r & 3;
        int gr = m0 - 1 + row;
        int kc16 = kc32 * 2 + (q >> 1);
        int ok = (gr >= 0 && gr < ROWS_PAD && kc16 < KR16);
        const unsigned short* src = (split ? Rl : Rh) +
            (ok ? ((size_t)gr * KPAD + kc32 * 32 + q * 8) : 0);
        uint32_t dst = soff +
            (uint32_t)((split * SA32_WORDS + row * 20 + q * 4) * 4);
        unsigned sz = ok ? 16u : 0u;
        asm volatile("cp.async.cg.shared.global [%0], [%1], 16, %2;"
                     :: "r"(dst), "l"(gptr(src)), "r"(sz) : "memory");
    }
    // B: two k16 sub-slices, 13 nf each (skip when beyond KR16; MMAs skipped too)
#pragma unroll
    for (int sub = 0; sub < 2; ++sub) {
        int kc16 = kc32 * 2 + sub;
        if (kc16 >= KR16) break;
        const unsigned int* bsrc = Bpk + ((size_t)kc16 * NFALL + ycol * 13) * 192;
#pragma unroll 1
        for (int i = tid; i < 624; i += 256) {
            uint32_t dst = soff +
                (uint32_t)((2 * SA32_WORDS + sub * 2496 + i * 4) * 4);
            asm volatile("cp.async.cg.shared.global [%0], [%1], 16, %2;"
                         :: "r"(dst), "l"(gptr(bsrc + i * 4)), "r"(16u) : "memory");
        }
    }
    asm volatile("cp.async.commit_group;" ::: "memory");
}

// ---------------- K3: tap-decomposed conv GEMM, fp16, k32 stages ------------
// CTA tile: M=128 x N=104; 8 warps x m16; 2-stage k32 cp.async ring (half the
// barriers of k16). Tail sub-chunk (zero K-pad) skipped at compile time.
template <int KPAD, int KR16, int COUT, int NFALL, int ONPAD, bool LAST>
__global__ void __launch_bounds__(256, 2)
conv_mma(const unsigned short* __restrict__ Rh, const unsigned short* __restrict__ Rl,
         const unsigned int* __restrict__ Bpk, const float* __restrict__ bias,
         unsigned short* __restrict__ Oh, unsigned short* __restrict__ Ol,
         float* __restrict__ Oc, float* __restrict__ Part) {
    extern __shared__ unsigned int smw[];
    const uint32_t sbase = smem_u32(smw);
    float* s_bias = reinterpret_cast<float*>(smw + OFF_BIAS32);

    const int tid = threadIdx.x, warp = tid >> 5, lane = tid & 31;
    const int m0  = blockIdx.x * 128;
    const int co0 = blockIdx.y * 104;
    if (tid < 104) s_bias[tid] = (co0 + tid < COUT) ? __ldg(&bias[co0 + tid]) : 0.f;

    float acc[13][4];
#pragma unroll
    for (int nf = 0; nf < 13; ++nf)
#pragma unroll
        for (int j = 0; j < 4; ++j) acc[nf][j] = 0.f;

    constexpr int NK32 = (KR16 + 1) / 2;
    conv_prefetch32<KPAD, KR16, NFALL>(Rh, Rl, Bpk, m0, blockIdx.y, 0, 0, tid, sbase);

    const int rowk = lane & 15;
    const uint32_t acolw4 = (uint32_t)((lane >> 4) * 16);   // byte offset within 16B pair

#pragma unroll
    for (int kc = 0; kc < NK32; ++kc) {
        cp_wait<0>();
        __syncthreads();
        const int st = kc & 1;
        const uint32_t aoff = sbase + (uint32_t)(st * STAGE32_WORDS * 4);
        const unsigned int* sbB = &smw[st * STAGE32_WORDS + 2 * SA32_WORDS];

        if (kc + 1 < NK32)
            conv_prefetch32<KPAD, KR16, NFALL>(Rh, Rl, Bpk, m0, blockIdx.y,
                                               kc + 1, st ^ 1, tid, sbase);

#pragma unroll
        for (int sub = 0; sub < 2; ++sub) {
            if (kc * 2 + sub >= KR16) continue;     // compile-time tail skip
            const uint32_t subcol = (uint32_t)(sub * 32);
            const unsigned int* sb = sbB + sub * 2496;

            uint32_t ah[2][4], al[2][4];
            {
                uint32_t ad = aoff +
                    (uint32_t)((warp * 16 + rowk) * 80) + subcol + acolw4;
                ldmx4(ah[0], ad);
                ldmx4(al[0], ad + SA32_WORDS * 4);
            }
#pragma unroll
            for (int tap = 0; tap < 3; ++tap) {
                const int cur = tap & 1, nxt = cur ^ 1;
                uint2 bb[13];
#pragma unroll
                for (int nf = 0; nf < 13; ++nf)
                    bb[nf] = *reinterpret_cast<const uint2*>(
                        &sb[(nf * 3 + tap) * 64 + lane * 2]);
                if (tap < 2) {   // prefetch next tap's A during this tap's MMAs
                    uint32_t ad = aoff +
                        (uint32_t)((warp * 16 + tap + 1 + rowk) * 80) + subcol + acolw4;
                    ldmx4(ah[nxt], ad);
                    ldmx4(al[nxt], ad + SA32_WORDS * 4);
                }
#pragma unroll
                for (int nf = 0; nf < 13; ++nf)
                    mma_f16(acc[nf], ah[cur], bb[nf].x, bb[nf].y);
#pragma unroll
                for (int nf = 0; nf < 13; ++nf)
                    mma_f16(acc[nf], al[cur], bb[nf].x, bb[nf].y);
            }
        }
    }

    // ---- staged epilogue ----
    __syncthreads();                 // all ldmatrix reads done; reuse smem
    if (LAST) {
        float* sOutF = reinterpret_cast<float*>(smw);   // [128][104]
#pragma unroll
        for (int nf = 0; nf < 13; ++nf)
#pragma unroll
            for (int j = 0; j < 4; ++j) {
                int row = warp * 16 + (lane >> 2) + (j >> 1) * 8;
                int n = nf * 8 + (lane & 3) * 2 + (j & 1);
                sOutF[row * 104 + n] = fmaxf(acc[nf][j] + s_bias[n], 0.f);
            }
        __syncthreads();
        for (int idx = tid; idx < 16 * 582; idx += 256) {
            int tl = idx / 582, r = idx - tl * 582;
            int co = r / 6, sl = r - co * 6;
            Oc[((size_t)(m0 >> 3) + tl) * 582 + r] =
                sOutF[(tl * 8 + sl + 1) * 104 + co];
        }
        // per-CTA BN partial sums (deterministic fixed order)
        if (tid < 97) {
            float s = 0.f, q = 0.f;
#pragma unroll 1
            for (int tl = 0; tl < 16; ++tl)
#pragma unroll
                for (int sl = 0; sl < 6; ++sl) {
                    float v = sOutF[(tl * 8 + sl + 1) * 104 + tid];
                    s += v;
                    q = fmaf(v, v, q);
                }
            Part[blockIdx.x * 194 + tid] = s;
            Part[blockIdx.x * 194 + 97 + tid] = q;
        }
    } else {
        unsigned short* sOut = reinterpret_cast<unsigned short*>(smw); // [2][128][104]
#pragma unroll
        for (int nf = 0; nf < 13; ++nf)
#pragma unroll
            for (int j = 0; j < 4; ++j) {
                int row = warp * 16 + (lane >> 2) + (j >> 1) * 8;
                int n = nf * 8 + (lane & 3) * 2 + (j & 1);
                float v = fmaxf(acc[nf][j] + s_bias[n], 0.f);
                unsigned short hb = f16_bits(v);
                sOut[row * 104 + n] = hb;
                sOut[13312 + row * 104 + n] = f16_bits(v - f16_val(hb));
            }
        __syncthreads();
        unsigned int* OhW = reinterpret_cast<unsigned int*>(Oh);
        unsigned int* OlW = reinterpret_cast<unsigned int*>(Ol);
        const unsigned int* sOutW = smw;
        for (int idx = tid; idx < 2 * 128 * 52; idx += 256) {
            int wd = idx % 52; int rest = idx / 52;
            int row = rest & 127; int arr = rest >> 7;
            int slot = row & 7;                    // m0 multiple of 128
            if (slot < 1 || slot > 6) continue;
            unsigned int val = sOutW[arr * 6656 + row * 52 + wd];
            unsigned int* dst = arr ? OlW : OhW;
            dst[(((size_t)(m0 + row) * ONPAD + co0) >> 1) + wd] = val;
        }
    }
}

// ---------------- K4: BN stats phase 2 (reduce 1024 partials/channel) ------
__global__ void bnstats2_kernel(const float* __restrict__ gamma,
                                const float* __restrict__ beta) {
    __shared__ double s_s[256], s_q[256];
    int n = blockIdx.x;
    double s = 0.0, q = 0.0;
    for (int i = threadIdx.x; i < 1024; i += 256) {
        s += (double)g_part[i * 194 + n];
        q += (double)g_part[i * 194 + 97 + n];
    }
    s_s[threadIdx.x] = s; s_q[threadIdx.x] = q;
    __syncthreads();
    for (int st = 128; st > 0; st >>= 1) {
        if (threadIdx.x < st) {
            s_s[threadIdx.x] += s_s[threadIdx.x + st];
            s_q[threadIdx.x] += s_q[threadIdx.x + st];
        }
        __syncthreads();
    }
    if (threadIdx.x == 0) {
        double N = (double)T_STEPS * 6.0;
        double mean = s_s[0] / N;
        double var = s_q[0] / N - mean * mean;
        float sc = gamma[n] * (float)(1.0 / sqrt(var + 1e-5));
        g_scale[n] = sc;
        g_shift[n] = beta[n] - (float)mean * sc;
    }
}

// ---------------- K5: fused BN apply + linear ------------------------------
__global__ void final_kernel(const float* __restrict__ Wl,
                             const float* __restrict__ bl,
                             float* __restrict__ out) {
    __shared__ float s_wl[36], s_bl[6];
    if (threadIdx.x < 36) s_wl[threadIdx.x] = Wl[threadIdx.x];
    if (threadIdx.x < 6)  s_bl[threadIdx.x] = bl[threadIdx.x];
    __syncthreads();

    int nt = blockIdx.x * blockDim.x + threadIdx.x;
    if (nt >= T_STEPS * NNODES) return;
    int n = nt % NNODES;
    float sc = __ldg(&g_scale[n]), sh = __ldg(&g_shift[n]);
    const float* p = &g_c3[(size_t)nt * 6];
    float v[6];
#pragma unroll
    for (int hh = 0; hh < 6; ++hh) v[hh] = fmaf(p[hh], sc, sh);
#pragma unroll
    for (int j = 0; j < 6; ++j) {
        float o = s_bl[j];
#pragma unroll
        for (int hh = 0; hh < 6; ++hh) o = fmaf(v[hh], s_wl[j * 6 + hh], o);
        out[nt * 6 + j] = o;
    }
}

// ---------------- launch ----------------------------------------------------
extern "C" void kernel_launch(void* const* d_in, const int* in_sizes, int n_in,
                              void* d_out, int out_size) {
    const float* X    = (const float*)d_in[1];
    const float* Wih  = (const float*)d_in[3];
    const float* Whh  = (const float*)d_in[4];
    const float* bih  = (const float*)d_in[5];
    const float* bhh  = (const float*)d_in[6];
    const float* Wc1  = (const float*)d_in[7];
    const float* bc1  = (const float*)d_in[8];
    const float* Wc2  = (const float*)d_in[9];
    const float* bc2  = (const float*)d_in[10];
    const float* Wc3  = (const float*)d_in[11];
    const float* bc3  = (const float*)d_in[12];
    const float* gamma = (const float*)d_in[13];
    const float* beta  = (const float*)d_in[14];
    const float* Wl   = (const float*)d_in[15];
    const float* bl   = (const float*)d_in[16];
    float* out = (float*)d_out;

    unsigned short *r1h, *r1l, *r2h, *r2l, *r3h, *r3l;
    unsigned int *b1, *b2, *b3;
    float *c3, *part;
    cudaGetSymbolAddress((void**)&r1h, g_R1h);
    cudaGetSymbolAddress((void**)&r1l, g_R1l);
    cudaGetSymbolAddress((void**)&r2h, g_R2h);
    cudaGetSymbolAddress((void**)&r2l, g_R2l);
    cudaGetSymbolAddress((void**)&r3h, g_R3h);
    cudaGetSymbolAddress((void**)&r3l, g_R3l);
    cudaGetSymbolAddress((void**)&b1, g_B1);
    cudaGetSymbolAddress((void**)&b2, g_B2);
    cudaGetSymbolAddress((void**)&b3, g_B3);
    cudaGetSymbolAddress((void**)&c3, g_c3);
    cudaGetSymbolAddress((void**)&part, g_part);

    cudaFuncSetAttribute(conv_mma<K1, 7, 194, 26, K23, false>,
                         cudaFuncAttributeMaxDynamicSharedMemorySize, CONV_SMEM32);
    cudaFuncSetAttribute(conv_mma<K23, 13, 194, 26, K23, false>,
                         cudaFuncAttributeMaxDynamicSharedMemorySize, CONV_SMEM32);
    cudaFuncSetAttribute(conv_mma<K23, 13, 97, 13, K23, true>,
                         cudaFuncAttributeMaxDynamicSharedMemorySize, CONV_SMEM32);

    const int NPACK = (7 * 26 + 13 * 26 + 13 * 13) * 192;
    pack_B<<<(NPACK + 255) / 256, 256>>>(Wc1, Wc2, Wc3);
    lstm_kernel<<<dim3(NCHUNK, 4), 160>>>(X, Wih, bih, bhh, Whh, r1h, r1l);
    conv_mma<K1, 7, 194, 26, K23, false>
        <<<dim3(1024, 2), 256, CONV_SMEM32>>>(r1h, r1l, b1, bc1, r2h, r2l, nullptr, nullptr);
    conv_mma<K23, 13, 194, 26, K23, false>
        <<<dim3(1024, 2), 256, CONV_SMEM32>>>(r2h, r2l, b2, bc2, r3h, r3l, nullptr, nullptr);
    conv_mma<K23, 13, 97, 13, K23, true>
        <<<dim3(1024, 1), 256, CONV_SMEM32>>>(r3h, r3l, b3, bc3, nullptr, nullptr, c3, part);
    bnstats2_kernel<<<97, 256>>>(gamma, beta);
    final_kernel<<<(T_STEPS * NNODES + 255) / 256, 256>>>(Wl, bl, out);
}

// round 16
// speedup vs baseline: 1.2145x; 1.0394x over previous
#include <cuda_runtime.h>
#include <cuda_fp16.h>
#include <math.h>
#include <stdint.h>

#define T_STEPS 16384
#define NNODES  97
#define HID     6
#define ROWS_PAD (T_STEPS * 8)     // 131072 padded rows (8 h-slots per t)

#define NCHUNK  128
#define CHUNK   128
#define WARM    64

#define K1   112                    // conv1 K: 97 ci -> pad 112 (7 k16 chunks)
#define K23  208                    // conv2/3 K: 194 -> pad 208 (13 chunks)

// conv smem layout (words): 2 stages of [A(hi)2600 | A(lo)2600 | B 4992]
#define SA32_WORDS    2600          // 130 rows * 20 words (80B stride, conflict-free)
#define STAGE32_WORDS 10192         // 2*2600 + 4992
#define OFF_BIAS32    20384         // 2 * 10192
#define CONV_SMEM32   ((OFF_BIAS32 + 104) * 4)   // 81952 bytes

// ---------------- scratch (device globals; zero-initialized .bss) ----------
__device__ unsigned short g_R1h[(size_t)ROWS_PAD * K1];
__device__ unsigned short g_R1l[(size_t)ROWS_PAD * K1];
__device__ unsigned short g_R2h[(size_t)ROWS_PAD * K23];
__device__ unsigned short g_R2l[(size_t)ROWS_PAD * K23];
__device__ unsigned short g_R3h[(size_t)ROWS_PAD * K23];
__device__ unsigned short g_R3l[(size_t)ROWS_PAD * K23];
__device__ float g_c3[(size_t)T_STEPS * 582];
__device__ float g_part[1024 * 194];
__device__ unsigned int g_B1[7  * 26 * 192];   // [kc16][nf][tap][lane][reg], fp16x2
__device__ unsigned int g_B2[13 * 26 * 192];
__device__ unsigned int g_B3[13 * 13 * 192];
__device__ float g_scale[NNODES];
__device__ float g_shift[NNODES];

// ---------------- helpers ---------------------------------------------------
__device__ __forceinline__ float sigf(float x) {
    return __fdividef(1.f, 1.f + __expf(-x));
}
// Branch-free tanh: 1 - 2/(e^{2x}+1). Correct limits at +/-inf, 2 MUFU.
__device__ __forceinline__ float tanh_f(float x) {
    float e = __expf(2.f * x);
    return 1.f - __fdividef(2.f, e + 1.f);
}
__device__ __forceinline__ uint32_t smem_u32(const void* p) {
    uint32_t a;
    asm("{ .reg .u64 t; cvta.to.shared.u64 t, %1; cvt.u32.u64 %0, t; }" : "=r"(a) : "l"(p));
    return a;
}
__device__ __forceinline__ uint64_t gptr(const void* p) {
    uint64_t g;
    asm("cvta.to.global.u64 %0, %1;" : "=l"(g) : "l"(p));
    return g;
}
__device__ __forceinline__ unsigned short f16_bits(float v) {
    __half h = __float2half_rn(v);
    return *reinterpret_cast<unsigned short*>(&h);
}
__device__ __forceinline__ float f16_val(unsigned short u) {
    __half h = *reinterpret_cast<__half*>(&u);
    return __half2float(h);
}
__device__ __forceinline__ void ldmx4(uint32_t* r, uint32_t addr) {
    asm volatile("ldmatrix.sync.aligned.m8n8.x4.shared.b16 {%0,%1,%2,%3}, [%4];"
                 : "=r"(r[0]), "=r"(r[1]), "=r"(r[2]), "=r"(r[3]) : "r"(addr));
}
__device__ __forceinline__ void mma_f16(float* d, const uint32_t* a, uint32_t b0, uint32_t b1) {
    asm volatile(
        "mma.sync.aligned.m16n8k16.row.col.f32.f16.f16.f32 "
        "{%0,%1,%2,%3}, {%4,%5,%6,%7}, {%8,%9}, {%0,%1,%2,%3};"
        : "+f"(d[0]), "+f"(d[1]), "+f"(d[2]), "+f"(d[3])
        : "r"(a[0]), "r"(a[1]), "r"(a[2]), "r"(a[3]), "r"(b0), "r"(b1));
}
template <int N>
__device__ __forceinline__ void cp_wait() {
    asm volatile("cp.async.wait_group %0;" :: "n"(N) : "memory");
}
__device__ __forceinline__ void cp16(uint32_t dst, uint64_t src, unsigned sz) {
    asm volatile("cp.async.cg.shared.global [%0], [%1], 16, %2;"
                 :: "r"(dst), "l"(src), "r"(sz) : "memory");
}

// ---------------- K0: pack tap weights into mma B-fragment layout (fp16) ----
__global__ void pack_B(const float* __restrict__ Wc1,
                       const float* __restrict__ Wc2,
                       const float* __restrict__ Wc3) {
    const int N1 = 7 * 26 * 192, N2 = 13 * 26 * 192, N3 = 13 * 13 * 192;
    int idx = blockIdx.x * 256 + threadIdx.x;
    const float* W; unsigned int* dst; int NFALL, CIN, COUT, li;
    if (idx < N1)           { W = Wc1; dst = g_B1; NFALL = 26; CIN = 97;  COUT = 194; li = idx; }
    else if (idx < N1 + N2) { W = Wc2; dst = g_B2; NFALL = 26; CIN = 194; COUT = 194; li = idx - N1; }
    else if (idx < N1 + N2 + N3) { W = Wc3; dst = g_B3; NFALL = 13; CIN = 194; COUT = 97; li = idx - N1 - N2; }
    else return;

    int reg   = li & 1;
    int lane  = (li >> 1) & 31;
    int tap   = (li >> 6) % 3;
    int nf    = (li / 192) % NFALL;
    int kc    = li / (192 * NFALL);

    int n  = nf * 8 + (lane >> 2);
    int k0 = kc * 16 + (lane & 3) * 2 + reg * 8;
    float w0 = 0.f, w1 = 0.f;
    if (n < COUT) {
        if (k0 < CIN)     w0 = W[((n * CIN + k0) * 3 + tap) * 3 + 1];
        if (k0 + 1 < CIN) w1 = W[((n * CIN + k0 + 1) * 3 + tap) * 3 + 1];
    }
    dst[li] = (unsigned int)f16_bits(w0) | ((unsigned int)f16_bits(w1) << 16);
}

// ---------------- K1: fused x-projection + chunked LSTM ---------------------
// Chains: 128-step chunks + 64-step warmup (restart err ~0.85^64 ~ 3e-5).
__global__ void lstm_kernel(const float* __restrict__ X,
                            const float* __restrict__ Wih,
                            const float* __restrict__ bih,
                            const float* __restrict__ bhh,
                            const float* __restrict__ Whh,
                            unsigned short* __restrict__ R1h,
                            unsigned short* __restrict__ R1l) {
    int lane = threadIdx.x & 31;
    int w    = threadIdx.x >> 5;
    int g    = lane / 6;
    int j    = lane % 6;
    int node = blockIdx.y * 25 + w * 5 + g;
    bool active = (lane < 30) && (node < NNODES);
    int nn = active ? node : 0;

    float Wx[4][12], Wr[4][6], bsum[4];
#pragma unroll
    for (int gi = 0; gi < 4; ++gi) {
        int row = gi * 6 + j;
        bsum[gi] = __ldg(&bih[row]) + __ldg(&bhh[row]);
#pragma unroll
        for (int f = 0; f < 12; ++f) Wx[gi][f] = __ldg(&Wih[row * 12 + f]);
#pragma unroll
        for (int k = 0; k < 6; ++k)  Wr[gi][k] = __ldg(&Whh[row * 6 + k]);
    }

    float h = 0.f, c = 0.f;
    int t0 = blockIdx.x * CHUNK;
    int tb = t0 - WARM; if (tb < 0) tb = 0;
    int te = t0 + CHUNK;
    int base = g * 6;

    float2 xs[2][8];
#pragma unroll
    for (int u = 0; u < 8; ++u)
        xs[0][u] = __ldg(reinterpret_cast<const float2*>(
            X + ((size_t)(tb + u) * NNODES + nn) * 12 + 2 * j));

    int pb = 0;
    for (int tB = tb; tB < te; tB += 8, pb ^= 1) {
        if (tB + 8 < te) {
#pragma unroll
            for (int u = 0; u < 8; ++u)
                xs[pb ^ 1][u] = __ldg(reinterpret_cast<const float2*>(
                    X + ((size_t)(tB + 8 + u) * NNODES + nn) * 12 + 2 * j));
        }
#pragma unroll
        for (int u = 0; u < 8; ++u) {
            int t = tB + u;
            float2 xp = xs[pb][u];
            float xv[12];
#pragma unroll
            for (int m = 0; m < 6; ++m) {
                xv[2 * m]     = __shfl_sync(0xffffffffu, xp.x, base + m);
                xv[2 * m + 1] = __shfl_sync(0xffffffffu, xp.y, base + m);
            }
            float gate[4];
#pragma unroll
            for (int gi = 0; gi < 4; ++gi) {
                float s = bsum[gi];
#pragma unroll
                for (int f = 0; f < 12; ++f) s = fmaf(Wx[gi][f], xv[f], s);
                gate[gi] = s;
            }
            float hs[6];
#pragma unroll
            for (int k = 0; k < 6; ++k) hs[k] = __shfl_sync(0xffffffffu, h, base + k);
#pragma unroll
            for (int k = 0; k < 6; ++k) {
                gate[0] = fmaf(Wr[0][k], hs[k], gate[0]);
                gate[1] = fmaf(Wr[1][k], hs[k], gate[1]);
                gate[2] = fmaf(Wr[2][k], hs[k], gate[2]);
                gate[3] = fmaf(Wr[3][k], hs[k], gate[3]);
            }
            float ai = sigf(gate[0]), af = sigf(gate[1]);
            float ag = tanh_f(gate[2]), ao = sigf(gate[3]);
            c = fmaf(af, c, ai * ag);
            h = tanh_f(ao * tanh_f(c));
            if (t >= t0 && active) {
                size_t p = ((size_t)t * 8 + j + 1) * K1 + node;
                unsigned short hb = f16_bits(h);
                R1h[p] = hb;
                R1l[p] = f16_bits(h - f16_val(hb));
            }
        }
    }
}

// ---------------- K3: tap-decomposed conv GEMM, fp16, k32 stages ------------
// CTA tile: M=128 x N=104; 8 warps x m16; 2-stage k32 cp.async ring.
// Prefetch addressing strength-reduced: per-thread A row offsets precomputed
// once (bit31 = zero-fill flag); per-stage item = add + cp.async issue.
template <int KPAD, int KR16, int COUT, int NFALL, int ONPAD, bool LAST>
__global__ void __launch_bounds__(256, 2)
conv_mma(const unsigned short* __restrict__ Rh, const unsigned short* __restrict__ Rl,
         const unsigned int* __restrict__ Bpk, const float* __restrict__ bias,
         unsigned short* __restrict__ Oh, unsigned short* __restrict__ Ol,
         float* __restrict__ Oc, float* __restrict__ Part) {
    extern __shared__ unsigned int smw[];
    const uint32_t sbase = smem_u32(smw);
    float* s_bias = reinterpret_cast<float*>(smw + OFF_BIAS32);

    const int tid = threadIdx.x, warp = tid >> 5, lane = tid & 31;
    const int m0  = blockIdx.x * 128;
    const int co0 = blockIdx.y * 104;
    if (tid < 104) s_bias[tid] = (co0 + tid < COUT) ? __ldg(&bias[co0 + tid]) : 0.f;

    // ---- prefetch state (computed once) ----
    const int aro = tid >> 3;                  // base row (0..31)
    const int asub = tid & 7;
    const int asplit = asub >> 2, aq = asub & 3;
    const unsigned short* Abase = asplit ? Rl : Rh;
    const int aqe = aq * 8;                    // element offset within k32 block
    uint32_t arow_off[5];
#pragma unroll
    for (int k = 0; k < 5; ++k) {
        int row = aro + 32 * k;
        int gr = m0 - 1 + row;
        bool ok = (gr >= 0) && (gr < ROWS_PAD);
        arow_off[k] = ok ? (uint32_t)gr * (uint32_t)KPAD : 0x80000000u;
    }
    const uint32_t adst0 = (uint32_t)((asplit * SA32_WORDS + aro * 20 + aq * 4) * 4);
    const bool aktail = (aq >> 1) != 0;        // this item belongs to sub-chunk 1
    const uint32_t y192 = (uint32_t)(blockIdx.y * 13) * 192u;

    auto prefetch = [&](int kc32, int stage) {
        const uint32_t soff = sbase + (uint32_t)(stage * STAGE32_WORDS * 4);
        const int acole = kc32 * 32 + aqe;
        const bool kok = (kc32 * 2 + (aktail ? 1 : 0)) < KR16;
#pragma unroll
        for (int k = 0; k < 5; ++k) {
            if (aro + 32 * k >= 130) break;
            uint32_t ro = arow_off[k];
            unsigned sz = (kok && !(ro & 0x80000000u)) ? 16u : 0u;
            cp16(soff + adst0 + (uint32_t)(k * 2560),
                 gptr(Abase + (ro & 0x7FFFFFFFu) + acole), sz);
        }
        // B: 624 x 16B items per k16 sub-slice (2496 words)
#pragma unroll
        for (int sub = 0; sub < 2; ++sub) {
            int kc16 = kc32 * 2 + sub;
            if (kc16 >= KR16) break;
            uint64_t bsrc = gptr(Bpk + (size_t)(kc16 * NFALL) * 192 + y192 + tid * 4);
            uint32_t bdst = soff + (uint32_t)((2 * SA32_WORDS + sub * 2496 + tid * 4) * 4);
#pragma unroll
            for (int k = 0; k < 3; ++k) {
                if (tid + 256 * k >= 624) break;
                cp16(bdst + (uint32_t)(k * 4096), bsrc + (uint64_t)(k * 4096), 16u);
            }
        }
        asm volatile("cp.async.commit_group;" ::: "memory");
    };

    float acc[13][4];
#pragma unroll
    for (int nf = 0; nf < 13; ++nf)
#pragma unroll
        for (int j = 0; j < 4; ++j) acc[nf][j] = 0.f;

    constexpr int NK32 = (KR16 + 1) / 2;
    prefetch(0, 0);

    const int rowk = lane & 15;
    const uint32_t acolw4 = (uint32_t)((lane >> 4) * 16);

#pragma unroll
    for (int kc = 0; kc < NK32; ++kc) {
        cp_wait<0>();
        __syncthreads();
        const int st = kc & 1;
        const uint32_t aoff = sbase + (uint32_t)(st * STAGE32_WORDS * 4);
        const unsigned int* sbB = &smw[st * STAGE32_WORDS + 2 * SA32_WORDS];

        if (kc + 1 < NK32) prefetch(kc + 1, st ^ 1);

#pragma unroll
        for (int sub = 0; sub < 2; ++sub) {
            if (kc * 2 + sub >= KR16) continue;   // compile-time tail skip
            const uint32_t subcol = (uint32_t)(sub * 32);
            const unsigned int* sb = sbB + sub * 2496;
#pragma unroll
            for (int tap = 0; tap < 3; ++tap) {
                uint2 bb[13];
#pragma unroll
                for (int nf = 0; nf < 13; ++nf)
                    bb[nf] = *reinterpret_cast<const uint2*>(
                        &sb[(nf * 3 + tap) * 64 + lane * 2]);
                uint32_t ah[4], al[4];
                uint32_t ad = aoff +
                    (uint32_t)((warp * 16 + tap + rowk) * 80) + subcol + acolw4;
                ldmx4(ah, ad);
                ldmx4(al, ad + SA32_WORDS * 4);
#pragma unroll
                for (int nf = 0; nf < 13; ++nf)
                    mma_f16(acc[nf], ah, bb[nf].x, bb[nf].y);
#pragma unroll
                for (int nf = 0; nf < 13; ++nf)
                    mma_f16(acc[nf], al, bb[nf].x, bb[nf].y);
            }
        }
    }

    // ---- staged epilogue ----
    __syncthreads();
    if (LAST) {
        float* sOutF = reinterpret_cast<float*>(smw);   // [128][104]
#pragma unroll
        for (int nf = 0; nf < 13; ++nf)
#pragma unroll
            for (int j = 0; j < 4; ++j) {
                int row = warp * 16 + (lane >> 2) + (j >> 1) * 8;
                int n = nf * 8 + (lane & 3) * 2 + (j & 1);
                sOutF[row * 104 + n] = fmaxf(acc[nf][j] + s_bias[n], 0.f);
            }
        __syncthreads();
        for (int idx = tid; idx < 16 * 582; idx += 256) {
            int tl = idx / 582, r = idx - tl * 582;
            int co = r / 6, sl = r - co * 6;
            Oc[((size_t)(m0 >> 3) + tl) * 582 + r] =
                sOutF[(tl * 8 + sl + 1) * 104 + co];
        }
        if (tid < 97) {
            float s = 0.f, q = 0.f;
#pragma unroll 1
            for (int tl = 0; tl < 16; ++tl)
#pragma unroll
                for (int sl = 0; sl < 6; ++sl) {
                    float v = sOutF[(tl * 8 + sl + 1) * 104 + tid];
                    s += v;
                    q = fmaf(v, v, q);
                }
            Part[blockIdx.x * 194 + tid] = s;
            Part[blockIdx.x * 194 + 97 + tid] = q;
        }
    } else {
        unsigned short* sOut = reinterpret_cast<unsigned short*>(smw); // [2][128][104]
#pragma unroll
        for (int nf = 0; nf < 13; ++nf)
#pragma unroll
            for (int j = 0; j < 4; ++j) {
                int row = warp * 16 + (lane >> 2) + (j >> 1) * 8;
                int n = nf * 8 + (lane & 3) * 2 + (j & 1);
                float v = fmaxf(acc[nf][j] + s_bias[n], 0.f);
                unsigned short hb = f16_bits(v);
                sOut[row * 104 + n] = hb;
                sOut[13312 + row * 104 + n] = f16_bits(v - f16_val(hb));
            }
        __syncthreads();
        unsigned int* OhW = reinterpret_cast<unsigned int*>(Oh);
        unsigned int* OlW = reinterpret_cast<unsigned int*>(Ol);
        const unsigned int* sOutW = smw;
        for (int idx = tid; idx < 2 * 128 * 52; idx += 256) {
            int wd = idx % 52; int rest = idx / 52;
            int row = rest & 127; int arr = rest >> 7;
            int slot = row & 7;
            if (slot < 1 || slot > 6) continue;
            unsigned int val = sOutW[arr * 6656 + row * 52 + wd];
            unsigned int* dst = arr ? OlW : OhW;
            dst[(((size_t)(m0 + row) * ONPAD + co0) >> 1) + wd] = val;
        }
    }
}

// ---------------- K4: BN stats phase 2 --------------------------------------
__global__ void bnstats2_kernel(const float* __restrict__ gamma,
                                const float* __restrict__ beta) {
    __shared__ double s_s[256], s_q[256];
    int n = blockIdx.x;
    double s = 0.0, q = 0.0;
    for (int i = threadIdx.x; i < 1024; i += 256) {
        s += (double)g_part[i * 194 + n];
        q += (double)g_part[i * 194 + 97 + n];
    }
    s_s[threadIdx.x] = s; s_q[threadIdx.x] = q;
    __syncthreads();
    for (int st = 128; st > 0; st >>= 1) {
        if (threadIdx.x < st) {
            s_s[threadIdx.x] += s_s[threadIdx.x + st];
            s_q[threadIdx.x] += s_q[threadIdx.x + st];
        }
        __syncthreads();
    }
    if (threadIdx.x == 0) {
        double N = (double)T_STEPS * 6.0;
        double mean = s_s[0] / N;
        double var = s_q[0] / N - mean * mean;
        float sc = gamma[n] * (float)(1.0 / sqrt(var + 1e-5));
        g_scale[n] = sc;
        g_shift[n] = beta[n] - (float)mean * sc;
    }
}

// ---------------- K5: fused BN apply + linear ------------------------------
__global__ void final_kernel(const float* __restrict__ Wl,
                             const float* __restrict__ bl,
                             float* __restrict__ out) {
    __shared__ float s_wl[36], s_bl[6];
    if (threadIdx.x < 36) s_wl[threadIdx.x] = Wl[threadIdx.x];
    if (threadIdx.x < 6)  s_bl[threadIdx.x] = bl[threadIdx.x];
    __syncthreads();

    int nt = blockIdx.x * blockDim.x + threadIdx.x;
    if (nt >= T_STEPS * NNODES) return;
    int n = nt % NNODES;
    float sc = __ldg(&g_scale[n]), sh = __ldg(&g_shift[n]);
    const float* p = &g_c3[(size_t)nt * 6];
    float v[6];
#pragma unroll
    for (int hh = 0; hh < 6; ++hh) v[hh] = fmaf(p[hh], sc, sh);
#pragma unroll
    for (int j = 0; j < 6; ++j) {
        float o = s_bl[j];
#pragma unroll
        for (int hh = 0; hh < 6; ++hh) o = fmaf(v[hh], s_wl[j * 6 + hh], o);
        out[nt * 6 + j] = o;
    }
}

// ---------------- launch ----------------------------------------------------
extern "C" void kernel_launch(void* const* d_in, const int* in_sizes, int n_in,
                              void* d_out, int out_size) {
    const float* X    = (const float*)d_in[1];
    const float* Wih  = (const float*)d_in[3];
    const float* Whh  = (const float*)d_in[4];
    const float* bih  = (const float*)d_in[5];
    const float* bhh  = (const float*)d_in[6];
    const float* Wc1  = (const float*)d_in[7];
    const float* bc1  = (const float*)d_in[8];
    const float* Wc2  = (const float*)d_in[9];
    const float* bc2  = (const float*)d_in[10];
    const float* Wc3  = (const float*)d_in[11];
    const float* bc3  = (const float*)d_in[12];
    const float* gamma = (const float*)d_in[13];
    const float* beta  = (const float*)d_in[14];
    const float* Wl   = (const float*)d_in[15];
    const float* bl   = (const float*)d_in[16];
    float* out = (float*)d_out;

    unsigned short *r1h, *r1l, *r2h, *r2l, *r3h, *r3l;
    unsigned int *b1, *b2, *b3;
    float *c3, *part;
    cudaGetSymbolAddress((void**)&r1h, g_R1h);
    cudaGetSymbolAddress((void**)&r1l, g_R1l);
    cudaGetSymbolAddress((void**)&r2h, g_R2h);
    cudaGetSymbolAddress((void**)&r2l, g_R2l);
    cudaGetSymbolAddress((void**)&r3h, g_R3h);
    cudaGetSymbolAddress((void**)&r3l, g_R3l);
    cudaGetSymbolAddress((void**)&b1, g_B1);
    cudaGetSymbolAddress((void**)&b2, g_B2);
    cudaGetSymbolAddress((void**)&b3, g_B3);
    cudaGetSymbolAddress((void**)&c3, g_c3);
    cudaGetSymbolAddress((void**)&part, g_part);

    cudaFuncSetAttribute(conv_mma<K1, 7, 194, 26, K23, false>,
                         cudaFuncAttributeMaxDynamicSharedMemorySize, CONV_SMEM32);
    cudaFuncSetAttribute(conv_mma<K23, 13, 194, 26, K23, false>,
                         cudaFuncAttributeMaxDynamicSharedMemorySize, CONV_SMEM32);
    cudaFuncSetAttribute(conv_mma<K23, 13, 97, 13, K23, true>,
                         cudaFuncAttributeMaxDynamicSharedMemorySize, CONV_SMEM32);

    const int NPACK = (7 * 26 + 13 * 26 + 13 * 13) * 192;
    pack_B<<<(NPACK + 255) / 256, 256>>>(Wc1, Wc2, Wc3);
    lstm_kernel<<<dim3(NCHUNK, 4), 160>>>(X, Wih, bih, bhh, Whh, r1h, r1l);
    conv_mma<K1, 7, 194, 26, K23, false>
        <<<dim3(1024, 2), 256, CONV_SMEM32>>>(r1h, r1l, b1, bc1, r2h, r2l, nullptr, nullptr);
    conv_mma<K23, 13, 194, 26, K23, false>
        <<<dim3(1024, 2), 256, CONV_SMEM32>>>(r2h, r2l, b2, bc2, r3h, r3l, nullptr, nullptr);
    conv_mma<K23, 13, 97, 13, K23, true>
        <<<dim3(1024, 1), 256, CONV_SMEM32>>>(r3h, r3l, b3, bc3, nullptr, nullptr, c3, part);
    bnstats2_kernel<<<97, 256>>>(gamma, beta);
    final_kernel<<<(T_STEPS * NNODES + 255) / 256, 256>>>(Wl, bl, out);
}